// round 5
// baseline (speedup 1.0000x reference)
#include <cuda_runtime.h>
#include <cuda_fp16.h>
#include <cstdint>

#define BATCH 16
#define HW    4096
#define C     256
#define D     32
#define DV    128
#define M_TOTAL (BATCH * HW)

#define TQ 128
#define TK 128
#define NTILES (HW / TK)
#define LOG2E 1.4426950408889634f

#define KROW 20     // K smem row stride (u32): 16 data + 4 pad (80B)
#define VROW 68     // V smem row stride (u32): 64 data + 4 pad (272B)
#define BUFB 55296  // attn smem bytes per pipeline buffer
#define KPAD 20     // GEMM smem row stride (u32) for 32-half rows

// ---- device scratch (no allocation allowed) ----
__device__ __align__(16) __half d_fh [(size_t)M_TOTAL * D];   // K hi
__device__ __align__(16) __half d_fl [(size_t)M_TOTAL * D];   // K lo
__device__ float                d_g  [(size_t)M_TOTAL * D];   // Q fp32
__device__ __align__(16) __half d_hn [(size_t)M_TOTAL * DV];  // V fp16 [m][dv]
__device__ __align__(16) __half d_obh[(size_t)M_TOTAL * DV];  // O hi
__device__ __align__(16) __half d_obl[(size_t)M_TOTAL * DV];  // O lo

// ---- helpers ----
__device__ __forceinline__ uint32_t packh2(float lo, float hi) {
    uint32_t r;
    asm("cvt.rn.f16x2.f32 %0, %1, %2;" : "=r"(r) : "f"(hi), "f"(lo));
    return r;
}
__device__ __forceinline__ void split2(float v0, float v1, uint32_t& hi, uint32_t& lo) {
    hi = packh2(v0, v1);
    __half2 h = *reinterpret_cast<__half2*>(&hi);
    float2 f = __half22float2(h);
    lo = packh2(v0 - f.x, v1 - f.y);
}
__device__ __forceinline__ void mma16816(float* c, const uint32_t* a,
                                         uint32_t b0, uint32_t b1) {
    asm volatile(
        "mma.sync.aligned.m16n8k16.row.col.f32.f16.f16.f32 "
        "{%0,%1,%2,%3}, {%4,%5,%6,%7}, {%8,%9}, {%0,%1,%2,%3};"
        : "+f"(c[0]), "+f"(c[1]), "+f"(c[2]), "+f"(c[3])
        : "r"(a[0]), "r"(a[1]), "r"(a[2]), "r"(a[3]), "r"(b0), "r"(b1));
}
__device__ __forceinline__ void cp16(uint32_t sdst, const void* gsrc) {
    asm volatile("cp.async.cg.shared.global [%0], [%1], 16;" :: "r"(sdst), "l"(gsrc));
}
__device__ __forceinline__ void ldsm4(uint32_t* r, uint32_t a) {
    asm volatile("ldmatrix.sync.aligned.m8n8.x4.shared.b16 {%0,%1,%2,%3}, [%4];"
                 : "=r"(r[0]), "=r"(r[1]), "=r"(r[2]), "=r"(r[3]) : "r"(a));
}
__device__ __forceinline__ void ldsm4t(uint32_t* r, uint32_t a) {
    asm volatile("ldmatrix.sync.aligned.m8n8.x4.trans.shared.b16 {%0,%1,%2,%3}, [%4];"
                 : "=r"(r[0]), "=r"(r[1]), "=r"(r[2]), "=r"(r[3]) : "r"(a));
}

// ---------------------------------------------------------------------------
// Flash attention: fp16 HMMA, ldmatrix fragments, register P, cp.async x2.
// smem buffer: Kh[128][80B] @0, Kl @10240, V[128 key][272B] @20480.
// ---------------------------------------------------------------------------
__global__ __launch_bounds__(256, 1) void attn_kernel() {
    extern __shared__ char sm[];
    const uint32_t smem_u32 = (uint32_t)__cvta_generic_to_shared(sm);

    const int b   = blockIdx.y;
    const int q0  = blockIdx.x * TQ;
    const int tid = threadIdx.x;
    const int w   = tid >> 5;
    const int lane = tid & 31;
    const int lr  = lane >> 2;
    const int lc  = lane & 3;

    // Q fragments (fp16 hi/lo, pre-scaled by log2e)
    uint32_t qh[2][4], ql[2][4];
    {
        const float* gq = d_g + ((size_t)b * HW + q0 + w * 16) * D;
        #pragma unroll
        for (int ks = 0; ks < 2; ks++) {
            #pragma unroll
            for (int r = 0; r < 4; r++) {
                const int row = (r & 1) ? (lr + 8) : lr;
                const int col = ks * 16 + ((r & 2) ? 8 : 0) + 2 * lc;
                const float v0 = gq[row * D + col]     * LOG2E;
                const float v1 = gq[row * D + col + 1] * LOG2E;
                split2(v0, v1, qh[ks][r], ql[ks][r]);
            }
        }
    }

    float o[16][4];
    #pragma unroll
    for (int nt = 0; nt < 16; nt++)
        o[nt][0] = o[nt][1] = o[nt][2] = o[nt][3] = 0.f;
    float lsum[4] = {0.f, 0.f, 0.f, 0.f};
    float mrow0 = -1e30f, mrow1 = -1e30f;

    auto issue_tile = [&](int t) {
        const uint32_t sb = smem_u32 + (t & 1) * BUFB;
        const int k0 = t * TK;
        #pragma unroll
        for (int i = 0; i < 4; i++) {            // K hi+lo
            const int idx = tid + 256 * i;
            const int arr = idx >> 9;
            const int row = (idx >> 2) & 127;
            const int c   = idx & 3;
            const __half* g = (arr ? d_fl : d_fh)
                              + ((size_t)(b * HW + k0 + row)) * D + c * 8;
            cp16(sb + arr * 10240 + row * 80 + c * 16, g);
        }
        #pragma unroll
        for (int i = 0; i < 8; i++) {            // V rows (256B each)
            const int idx = tid + 256 * i;
            const int row = idx >> 4;
            const int c   = idx & 15;
            const __half* g = d_hn + ((size_t)(b * HW + k0 + row)) * DV + c * 8;
            cp16(sb + 20480 + row * 272 + c * 16, g);
        }
        asm volatile("cp.async.commit_group;");
    };

    // per-thread ldmatrix base offsets
    const uint32_t koff = ((lane & 7) * KROW + (lane >> 3) * 4) * 4;
    const uint32_t voff = ((lane & 15) * VROW) * 4 + (lane >> 4) * 16;

    issue_tile(0);

    #pragma unroll 1
    for (int t = 0; t < NTILES; t++) {
        if (t + 1 < NTILES) {
            issue_tile(t + 1);
            asm volatile("cp.async.wait_group 1;");
        } else {
            asm volatile("cp.async.wait_group 0;");
        }
        __syncthreads();

        const uint32_t sb = smem_u32 + (t & 1) * BUFB;
        const uint32_t khb = sb + koff;
        const uint32_t vb  = sb + 20480 + voff;

        // ---- S = Q K^T (2-term split) ----
        float s[16][4];
        #pragma unroll
        for (int nt = 0; nt < 16; nt++) {
            uint32_t kh[4], kl[4];
            ldsm4(kh, khb + nt * 640);
            ldsm4(kl, khb + 10240 + nt * 640);
            s[nt][0] = s[nt][1] = s[nt][2] = s[nt][3] = 0.f;
            mma16816(s[nt], qh[0], kh[0], kh[1]);
            mma16816(s[nt], ql[0], kh[0], kh[1]);
            mma16816(s[nt], qh[0], kl[0], kl[1]);
            mma16816(s[nt], qh[1], kh[2], kh[3]);
            mma16816(s[nt], ql[1], kh[2], kh[3]);
            mma16816(s[nt], qh[1], kl[2], kl[3]);
        }

        // ---- online softmax (log2 domain) ----
        float mx0 = fmaxf(s[0][0], s[0][1]);
        float mx1 = fmaxf(s[0][2], s[0][3]);
        #pragma unroll
        for (int nt = 1; nt < 16; nt++) {
            mx0 = fmaxf(mx0, fmaxf(s[nt][0], s[nt][1]));
            mx1 = fmaxf(mx1, fmaxf(s[nt][2], s[nt][3]));
        }
        mx0 = fmaxf(mx0, __shfl_xor_sync(0xffffffffu, mx0, 1));
        mx0 = fmaxf(mx0, __shfl_xor_sync(0xffffffffu, mx0, 2));
        mx1 = fmaxf(mx1, __shfl_xor_sync(0xffffffffu, mx1, 1));
        mx1 = fmaxf(mx1, __shfl_xor_sync(0xffffffffu, mx1, 2));

        const float mn0 = fmaxf(mrow0, mx0);
        const float mn1 = fmaxf(mrow1, mx1);
        const float corr0 = exp2f(mrow0 - mn0);
        const float corr1 = exp2f(mrow1 - mn1);
        mrow0 = mn0; mrow1 = mn1;

        uint32_t pa[8][4];
        #pragma unroll
        for (int nt = 0; nt < 16; nt++) {
            const float p0 = exp2f(s[nt][0] - mn0);
            const float p1 = exp2f(s[nt][1] - mn0);
            const float p2 = exp2f(s[nt][2] - mn1);
            const float p3 = exp2f(s[nt][3] - mn1);
            pa[nt >> 1][(nt & 1) ? 2 : 0] = packh2(p0, p1);
            pa[nt >> 1][(nt & 1) ? 3 : 1] = packh2(p2, p3);
        }

        lsum[0] *= corr0; lsum[2] *= corr1;
        #pragma unroll
        for (int nt = 0; nt < 16; nt++) {
            o[nt][0] *= corr0; o[nt][1] *= corr0;
            o[nt][2] *= corr1; o[nt][3] *= corr1;
        }

        // ---- O += P V ----
        const uint32_t ONES = 0x3C003C00u;
        #pragma unroll
        for (int ks = 0; ks < 8; ks++) {
            mma16816(lsum, pa[ks], ONES, ONES);
            const uint32_t vrow = vb + ks * 4352;   // 16 rows * 272B
            #pragma unroll
            for (int ntp = 0; ntp < 8; ntp++) {
                uint32_t v[4];
                ldsm4t(v, vrow + ntp * 32);
                mma16816(o[2 * ntp],     pa[ks], v[0], v[1]);
                mma16816(o[2 * ntp + 1], pa[ks], v[2], v[3]);
            }
        }
        __syncthreads();
    }

    // ---- normalize + store fp16 hi/lo ----
    const float inv0 = 1.f / lsum[0];
    const float inv1 = 1.f / lsum[2];
    uint32_t* goh = (uint32_t*)d_obh + ((size_t)b * HW + q0 + w * 16) * 64;
    uint32_t* gol = (uint32_t*)d_obl + ((size_t)b * HW + q0 + w * 16) * 64;
    #pragma unroll
    for (int nt = 0; nt < 16; nt++) {
        uint32_t hi, lo;
        split2(o[nt][0] * inv0, o[nt][1] * inv0, hi, lo);
        goh[lr * 64 + nt * 4 + lc] = hi;
        gol[lr * 64 + nt * 4 + lc] = lo;
        split2(o[nt][2] * inv1, o[nt][3] * inv1, hi, lo);
        goh[(lr + 8) * 64 + nt * 4 + lc] = hi;
        gol[(lr + 8) * 64 + nt * 4 + lc] = lo;
    }
}

// ---------------------------------------------------------------------------
// Projections (tensor core): [65536,256] @ [256,192], 2-term fp16 split.
// grid (512, 3): by=0 -> f+g (cols 0..63), by=1,2 -> h (dv 0..127).
// Block tile 128m x 64n; 8 warps as 4m x 2n (warp tile 32x32).
// ---------------------------------------------------------------------------
__global__ __launch_bounds__(256) void proj_kernel(
    const float* __restrict__ x,
    const float* __restrict__ Wf, const float* __restrict__ bf,
    const float* __restrict__ Wg, const float* __restrict__ bg,
    const float* __restrict__ Wh, const float* __restrict__ bh)
{
    __shared__ uint32_t sXh[128 * KPAD];
    __shared__ uint32_t sXl[128 * KPAD];
    __shared__ uint32_t sWh[64 * KPAD];
    __shared__ uint32_t sWl[64 * KPAD];

    const int m0 = blockIdx.x * 128;
    const int by = blockIdx.y;
    const int n0 = by * 64;
    const int tid = threadIdx.x;
    const int lane = tid & 31;
    const int w = tid >> 5;
    const int warpM = (w >> 1) * 32;
    const int warpN = (w & 1) * 32;
    const int lr = lane >> 2, lc = lane & 3;

    const uint32_t xh_s = (uint32_t)__cvta_generic_to_shared(sXh);
    const uint32_t xl_s = (uint32_t)__cvta_generic_to_shared(sXl);
    const uint32_t wh_s = (uint32_t)__cvta_generic_to_shared(sWh);
    const uint32_t wl_s = (uint32_t)__cvta_generic_to_shared(sWl);

    float4 xr[4];
    float  wr[8];
    auto loadX = [&](int k0) {
        #pragma unroll
        for (int q = 0; q < 4; q++) {
            const int fidx = tid + 256 * q;
            const int row = fidx >> 3, cc = fidx & 7;
            xr[q] = *(const float4*)&x[(size_t)(m0 + row) * C + k0 + cc * 4];
        }
    };
    auto loadW = [&](int k0) {
        #pragma unroll
        for (int q = 0; q < 8; q++) {
            const int widx = tid + 256 * q;
            const int kk = widx >> 6, nn = widx & 63;
            const int j = n0 + nn;
            wr[q] = (j < 32) ? Wf[(size_t)(k0 + kk) * 32 + j]
                  : (j < 64) ? Wg[(size_t)(k0 + kk) * 32 + (j - 32)]
                             : Wh[(size_t)(k0 + kk) * 128 + (j - 64)];
        }
    };

    float cfr[2][4][4];
    #pragma unroll
    for (int mt = 0; mt < 2; mt++)
        #pragma unroll
        for (int nt = 0; nt < 4; nt++)
            cfr[mt][nt][0] = cfr[mt][nt][1] = cfr[mt][nt][2] = cfr[mt][nt][3] = 0.f;

    loadX(0); loadW(0);

    #pragma unroll 1
    for (int s = 0; s < 8; s++) {
        __syncthreads();
        #pragma unroll
        for (int q = 0; q < 4; q++) {
            const int fidx = tid + 256 * q;
            const int row = fidx >> 3, cc = fidx & 7;
            uint32_t h0, l0, h1, l1;
            split2(xr[q].x, xr[q].y, h0, l0);
            split2(xr[q].z, xr[q].w, h1, l1);
            sXh[row * KPAD + cc * 2]     = h0;
            sXh[row * KPAD + cc * 2 + 1] = h1;
            sXl[row * KPAD + cc * 2]     = l0;
            sXl[row * KPAD + cc * 2 + 1] = l1;
        }
        {
            __half* swh = (__half*)sWh;
            __half* swl = (__half*)sWl;
            #pragma unroll
            for (int q = 0; q < 8; q++) {
                const int widx = tid + 256 * q;
                const int kk = widx >> 6, nn = widx & 63;
                const __half hv = __float2half_rn(wr[q]);
                swh[nn * 40 + kk] = hv;
                swl[nn * 40 + kk] = __float2half_rn(wr[q] - __half2float(hv));
            }
        }
        __syncthreads();
        if (s < 7) { loadX((s + 1) * 32); loadW((s + 1) * 32); }

        #pragma unroll
        for (int kf = 0; kf < 2; kf++) {
            uint32_t ah[2][4], al[2][4];
            #pragma unroll
            for (int mt = 0; mt < 2; mt++) {
                const uint32_t off =
                    ((warpM + mt * 16 + (lane & 15)) * KPAD + kf * 8 + (lane >> 4) * 4) * 4;
                ldsm4(ah[mt], xh_s + off);
                ldsm4(al[mt], xl_s + off);
            }
            uint32_t bh_[2][4], bl_[2][4];
            #pragma unroll
            for (int ntp = 0; ntp < 2; ntp++) {
                const uint32_t boff =
                    ((warpN + ntp * 16 + (lane & 7) + (lane >> 4) * 8) * KPAD
                     + kf * 8 + ((lane >> 3) & 1) * 4) * 4;
                ldsm4(bh_[ntp], wh_s + boff);
                ldsm4(bl_[ntp], wl_s + boff);
            }
            #pragma unroll
            for (int mt = 0; mt < 2; mt++)
                #pragma unroll
                for (int nt = 0; nt < 4; nt++) {
                    const uint32_t b0 = bh_[nt >> 1][(nt & 1) * 2];
                    const uint32_t b1 = bh_[nt >> 1][(nt & 1) * 2 + 1];
                    const uint32_t c0 = bl_[nt >> 1][(nt & 1) * 2];
                    const uint32_t c1 = bl_[nt >> 1][(nt & 1) * 2 + 1];
                    mma16816(cfr[mt][nt], ah[mt], b0, b1);
                    mma16816(cfr[mt][nt], al[mt], b0, b1);
                    mma16816(cfr[mt][nt], ah[mt], c0, c1);
                }
        }
    }

    // epilogue with routing
    #pragma unroll
    for (int mt = 0; mt < 2; mt++) {
        const size_t mA = (size_t)(m0 + warpM + mt * 16 + lr);
        const size_t mB = mA + 8;
        #pragma unroll
        for (int nt = 0; nt < 4; nt++) {
            const int jl = warpN + nt * 8 + 2 * lc;
            const float c0 = cfr[mt][nt][0], c1 = cfr[mt][nt][1];
            const float c2 = cfr[mt][nt][2], c3 = cfr[mt][nt][3];
            if (by == 0) {
                if (jl < 32) {
                    const float b0v = bf[jl], b1v = bf[jl + 1];
                    uint32_t hi, lo;
                    split2(c0 + b0v, c1 + b1v, hi, lo);
                    ((uint32_t*)d_fh)[mA * 16 + (jl >> 1)] = hi;
                    ((uint32_t*)d_fl)[mA * 16 + (jl >> 1)] = lo;
                    split2(c2 + b0v, c3 + b1v, hi, lo);
                    ((uint32_t*)d_fh)[mB * 16 + (jl >> 1)] = hi;
                    ((uint32_t*)d_fl)[mB * 16 + (jl >> 1)] = lo;
                } else {
                    const int jj = jl - 32;
                    const float b0v = bg[jj], b1v = bg[jj + 1];
                    *(float2*)&d_g[mA * D + jj] = make_float2(c0 + b0v, c1 + b1v);
                    *(float2*)&d_g[mB * D + jj] = make_float2(c2 + b0v, c3 + b1v);
                }
            } else {
                const int dv = (by - 1) * 64 + jl;
                const float b0v = bh[dv], b1v = bh[dv + 1];
                ((uint32_t*)d_hn)[mA * 64 + (dv >> 1)] = packh2(c0 + b0v, c1 + b1v);
                ((uint32_t*)d_hn)[mB * 64 + (dv >> 1)] = packh2(c2 + b0v, c3 + b1v);
            }
        }
    }
}

// ---------------------------------------------------------------------------
// Output projection (tensor core) + residual: out = x + O @ Wo + bo.
// O is fp16 hi/lo from attention. Block 128m x 128n; warps 2m x 4n (64x32).
// smem: A buf0 hi@0 lo@10240, buf1 @20480, Wh @40960, Wl @51200 (61440 B).
// ---------------------------------------------------------------------------
__global__ __launch_bounds__(256, 1) void outproj_kernel(
    const float* __restrict__ x,
    const float* __restrict__ Wo,
    const float* __restrict__ bo,
    float* __restrict__ out)
{
    extern __shared__ char smo[];
    const uint32_t sbase = (uint32_t)__cvta_generic_to_shared(smo);

    const int m0 = blockIdx.x * 128;
    const int n0 = blockIdx.y * 128;
    const int tid = threadIdx.x;
    const int lane = tid & 31;
    const int w = tid >> 5;
    const int warpM = (w >> 2) * 64;
    const int warpN = (w & 3) * 32;
    const int lr = lane >> 2, lc = lane & 3;

    auto issueA = [&](int s) {
        const uint32_t db = sbase + (s & 1) * 20480;
        #pragma unroll
        for (int i = 0; i < 4; i++) {
            const int idx = tid + 256 * i;
            const int arr = idx >> 9;
            const int rem = idx & 511;
            const int row = rem >> 2, cc = rem & 3;
            const uint32_t* src = (const uint32_t*)(arr ? d_obl : d_obh)
                                  + (size_t)(m0 + row) * 64 + s * 16 + cc * 4;
            cp16(db + arr * 10240 + row * 80 + cc * 16, src);
        }
        asm volatile("cp.async.commit_group;");
    };

    float4 wr4[4];
    auto loadW = [&](int s) {
        const int k0 = s * 32;
        #pragma unroll
        for (int q = 0; q < 4; q++) {
            const int fidx = tid + 256 * q;
            const int kk = fidx >> 5, c4 = fidx & 31;
            wr4[q] = *(const float4*)&Wo[(size_t)(k0 + kk) * C + n0 + c4 * 4];
        }
    };

    float cfr[4][4][4];
    #pragma unroll
    for (int mt = 0; mt < 4; mt++)
        #pragma unroll
        for (int nt = 0; nt < 4; nt++)
            cfr[mt][nt][0] = cfr[mt][nt][1] = cfr[mt][nt][2] = cfr[mt][nt][3] = 0.f;

    issueA(0);
    loadW(0);

    #pragma unroll 1
    for (int s = 0; s < 4; s++) {
        if (s < 3) {
            issueA(s + 1);
            asm volatile("cp.async.wait_group 1;");
        } else {
            asm volatile("cp.async.wait_group 0;");
        }
        __syncthreads();
        {
            __half* swh = (__half*)(smo + 40960);
            __half* swl = (__half*)(smo + 51200);
            #pragma unroll
            for (int q = 0; q < 4; q++) {
                const int fidx = tid + 256 * q;
                const int kk = fidx >> 5, c4 = fidx & 31;
                const float4 v = wr4[q];
                #pragma unroll
                for (int e = 0; e < 4; e++) {
                    const float val = (&v.x)[e];
                    const int nn = c4 * 4 + e;
                    const __half hv = __float2half_rn(val);
                    swh[nn * 40 + kk] = hv;
                    swl[nn * 40 + kk] = __float2half_rn(val - __half2float(hv));
                }
            }
        }
        __syncthreads();
        if (s < 3) loadW(s + 1);

        const uint32_t ab = sbase + (s & 1) * 20480;
        const uint32_t wb = sbase + 40960;
        #pragma unroll
        for (int kf = 0; kf < 2; kf++) {
            uint32_t ah[4][4], al[4][4];
            #pragma unroll
            for (int mt = 0; mt < 4; mt++) {
                const uint32_t off =
                    ((warpM + mt * 16 + (lane & 15)) * KPAD + kf * 8 + (lane >> 4) * 4) * 4;
                ldsm4(ah[mt], ab + off);
                ldsm4(al[mt], ab + 10240 + off);
            }
            uint32_t bh_[2][4], bl_[2][4];
            #pragma unroll
            for (int ntp = 0; ntp < 2; ntp++) {
                const uint32_t boff =
                    ((warpN + ntp * 16 + (lane & 7) + (lane >> 4) * 8) * KPAD
                     + kf * 8 + ((lane >> 3) & 1) * 4) * 4;
                ldsm4(bh_[ntp], wb + boff);
                ldsm4(bl_[ntp], wb + 10240 + boff);
            }
            #pragma unroll
            for (int mt = 0; mt < 4; mt++)
                #pragma unroll
                for (int nt = 0; nt < 4; nt++) {
                    const uint32_t b0 = bh_[nt >> 1][(nt & 1) * 2];
                    const uint32_t b1 = bh_[nt >> 1][(nt & 1) * 2 + 1];
                    const uint32_t c0 = bl_[nt >> 1][(nt & 1) * 2];
                    const uint32_t c1 = bl_[nt >> 1][(nt & 1) * 2 + 1];
                    mma16816(cfr[mt][nt], ah[mt], b0, b1);
                    mma16816(cfr[mt][nt], al[mt], b0, b1);
                    mma16816(cfr[mt][nt], ah[mt], c0, c1);
                }
        }
        __syncthreads();
    }

    // epilogue: bias + residual
    #pragma unroll
    for (int mt = 0; mt < 4; mt++) {
        const size_t mA = (size_t)(m0 + warpM + mt * 16 + lr);
        const size_t mB = mA + 8;
        #pragma unroll
        for (int nt = 0; nt < 4; nt++) {
            const int j = n0 + warpN + nt * 8 + 2 * lc;
            const float b0v = bo[j], b1v = bo[j + 1];
            const float2 xa = *(const float2*)&x[mA * C + j];
            const float2 xb = *(const float2*)&x[mB * C + j];
            *(float2*)&out[mA * C + j] =
                make_float2(xa.x + cfr[mt][nt][0] + b0v, xa.y + cfr[mt][nt][1] + b1v);
            *(float2*)&out[mB * C + j] =
                make_float2(xb.x + cfr[mt][nt][2] + b0v, xb.y + cfr[mt][nt][3] + b1v);
        }
    }
}

// ---------------------------------------------------------------------------
extern "C" void kernel_launch(void* const* d_in, const int* in_sizes, int n_in,
                              void* d_out, int out_size)
{
    const float* x  = (const float*)d_in[0];
    const float* Wf = (const float*)d_in[1];
    const float* bf = (const float*)d_in[2];
    const float* Wg = (const float*)d_in[3];
    const float* bg = (const float*)d_in[4];
    const float* Wh = (const float*)d_in[5];
    const float* bh = (const float*)d_in[6];
    const float* Wo = (const float*)d_in[7];
    const float* bo = (const float*)d_in[8];
    float* out = (float*)d_out;

    proj_kernel<<<dim3(M_TOTAL / 128, 3), 256>>>(x, Wf, bf, Wg, bg, Wh, bh);

    const int smem_attn = 2 * BUFB;   // 110592
    cudaFuncSetAttribute(attn_kernel,
                         cudaFuncAttributeMaxDynamicSharedMemorySize, smem_attn);
    attn_kernel<<<dim3(HW / TQ, BATCH), 256, smem_attn>>>();

    const int smem_op = 61440;
    cudaFuncSetAttribute(outproj_kernel,
                         cudaFuncAttributeMaxDynamicSharedMemorySize, smem_op);
    outproj_kernel<<<dim3(M_TOTAL / 128, C / 128), 256, smem_op>>>(x, Wo, bo, out);
}

// round 7
// speedup vs baseline: 1.2647x; 1.2647x over previous
#include <cuda_runtime.h>
#include <cuda_fp16.h>
#include <cstdint>

#define BATCH 16
#define HW    4096
#define C     256
#define D     32
#define DV    128
#define M_TOTAL (BATCH * HW)

#define TQ 128
#define TK 128
#define NTILES (HW / TK)
#define LOG2E 1.4426950408889634f

#define KROW 20     // attn K smem row stride (u32)
#define VROW 68     // attn V smem row stride (u32)
#define BUFB 55296  // attn smem bytes per buffer

// ---- device scratch (no allocation allowed) ----
__device__ __align__(16) __half d_xh [(size_t)M_TOTAL * C];   // x hi
__device__ __align__(16) __half d_xl [(size_t)M_TOTAL * C];   // x lo
__device__ __align__(16) __half d_wph[192 * C];               // proj W hi [n][k]
__device__ __align__(16) __half d_wpl[192 * C];               // proj W lo [n][k]
__device__ __align__(16) __half d_woh[C * DV];                // Wo hi [n][k]
__device__ __align__(16) __half d_wol[C * DV];                // Wo lo [n][k]
__device__ __align__(16) __half d_fh [(size_t)M_TOTAL * D];   // K hi
__device__ __align__(16) __half d_fl [(size_t)M_TOTAL * D];   // K lo
__device__ float                d_g  [(size_t)M_TOTAL * D];   // Q fp32
__device__ __align__(16) __half d_hn [(size_t)M_TOTAL * DV];  // V fp16 [m][dv]
__device__ __align__(16) __half d_obh[(size_t)M_TOTAL * DV];  // O hi
__device__ __align__(16) __half d_obl[(size_t)M_TOTAL * DV];  // O lo

// ---- helpers ----
__device__ __forceinline__ uint32_t packh2(float lo, float hi) {
    uint32_t r;
    asm("cvt.rn.f16x2.f32 %0, %1, %2;" : "=r"(r) : "f"(hi), "f"(lo));
    return r;
}
__device__ __forceinline__ void split2(float v0, float v1, uint32_t& hi, uint32_t& lo) {
    hi = packh2(v0, v1);
    __half2 h = *reinterpret_cast<__half2*>(&hi);
    float2 f = __half22float2(h);
    lo = packh2(v0 - f.x, v1 - f.y);
}
__device__ __forceinline__ void mma16816(float* c, const uint32_t* a,
                                         uint32_t b0, uint32_t b1) {
    asm volatile(
        "mma.sync.aligned.m16n8k16.row.col.f32.f16.f16.f32 "
        "{%0,%1,%2,%3}, {%4,%5,%6,%7}, {%8,%9}, {%0,%1,%2,%3};"
        : "+f"(c[0]), "+f"(c[1]), "+f"(c[2]), "+f"(c[3])
        : "r"(a[0]), "r"(a[1]), "r"(a[2]), "r"(a[3]), "r"(b0), "r"(b1));
}
__device__ __forceinline__ void cp16(uint32_t sdst, const void* gsrc) {
    asm volatile("cp.async.cg.shared.global [%0], [%1], 16;" :: "r"(sdst), "l"(gsrc));
}
__device__ __forceinline__ void ldsm4(uint32_t* r, uint32_t a) {
    asm volatile("ldmatrix.sync.aligned.m8n8.x4.shared.b16 {%0,%1,%2,%3}, [%4];"
                 : "=r"(r[0]), "=r"(r[1]), "=r"(r[2]), "=r"(r[3]) : "r"(a));
}
__device__ __forceinline__ void ldsm4t(uint32_t* r, uint32_t a) {
    asm volatile("ldmatrix.sync.aligned.m8n8.x4.trans.shared.b16 {%0,%1,%2,%3}, [%4];"
                 : "=r"(r[0]), "=r"(r[1]), "=r"(r[2]), "=r"(r[3]) : "r"(a));
}

// ---------------------------------------------------------------------------
// Pre-split: x -> fp16 hi/lo
// ---------------------------------------------------------------------------
__global__ __launch_bounds__(256) void presplit_x_kernel(const float* __restrict__ x) {
    const size_t NX4 = (size_t)M_TOTAL * C / 4;
    const size_t stride = (size_t)gridDim.x * blockDim.x;
    for (size_t i = (size_t)blockIdx.x * blockDim.x + threadIdx.x; i < NX4; i += stride) {
        float4 v = ((const float4*)x)[i];
        uint32_t h0, l0, h1, l1;
        split2(v.x, v.y, h0, l0);
        split2(v.z, v.w, h1, l1);
        ((uint2*)d_xh)[i] = make_uint2(h0, h1);
        ((uint2*)d_xl)[i] = make_uint2(l0, l1);
    }
}

// Pre-split + transpose weights: proj W -> [192 n][256 k], Wo -> [256 n][128 k]
__global__ __launch_bounds__(256) void presplit_w_kernel(
    const float* __restrict__ Wf, const float* __restrict__ Wg,
    const float* __restrict__ Wh, const float* __restrict__ Wo)
{
    const int t = blockIdx.x * blockDim.x + threadIdx.x;
    if (t < 192 * 256) {
        const int n = t >> 8, k = t & 255;
        const float v = (n < 32) ? Wf[k * 32 + n]
                      : (n < 64) ? Wg[k * 32 + (n - 32)]
                                 : Wh[k * 128 + (n - 64)];
        const __half hv = __float2half_rn(v);
        d_wph[t] = hv;
        d_wpl[t] = __float2half_rn(v - __half2float(hv));
    }
    const int t2 = t - 192 * 256;
    if (t2 >= 0 && t2 < 256 * 128) {
        const int n = t2 >> 7, k = t2 & 127;
        const float v = Wo[k * 256 + n];
        const __half hv = __float2half_rn(v);
        d_woh[t2] = hv;
        d_wol[t2] = __float2half_rn(v - __half2float(hv));
    }
}

// ---------------------------------------------------------------------------
// Flash attention (unchanged structure; ex2.approx.f16x2 softmax).
// ---------------------------------------------------------------------------
__global__ __launch_bounds__(256, 1) void attn_kernel() {
    extern __shared__ char sm[];
    const uint32_t smem_u32 = (uint32_t)__cvta_generic_to_shared(sm);

    const int b   = blockIdx.y;
    const int q0  = blockIdx.x * TQ;
    const int tid = threadIdx.x;
    const int w   = tid >> 5;
    const int lane = tid & 31;
    const int lr  = lane >> 2;
    const int lc  = lane & 3;

    uint32_t qh[2][4], ql[2][4];
    {
        const float* gq = d_g + ((size_t)b * HW + q0 + w * 16) * D;
        #pragma unroll
        for (int ks = 0; ks < 2; ks++) {
            #pragma unroll
            for (int r = 0; r < 4; r++) {
                const int row = (r & 1) ? (lr + 8) : lr;
                const int col = ks * 16 + ((r & 2) ? 8 : 0) + 2 * lc;
                const float v0 = gq[row * D + col]     * LOG2E;
                const float v1 = gq[row * D + col + 1] * LOG2E;
                split2(v0, v1, qh[ks][r], ql[ks][r]);
            }
        }
    }

    float o[16][4];
    #pragma unroll
    for (int nt = 0; nt < 16; nt++)
        o[nt][0] = o[nt][1] = o[nt][2] = o[nt][3] = 0.f;
    float lsum[4] = {0.f, 0.f, 0.f, 0.f};
    float mrow0 = -1e30f, mrow1 = -1e30f;

    auto issue_tile = [&](int t) {
        const uint32_t sb = smem_u32 + (t & 1) * BUFB;
        const int k0 = t * TK;
        #pragma unroll
        for (int i = 0; i < 4; i++) {
            const int idx = tid + 256 * i;
            const int arr = idx >> 9;
            const int row = (idx >> 2) & 127;
            const int c   = idx & 3;
            const __half* g = (arr ? d_fl : d_fh)
                              + ((size_t)(b * HW + k0 + row)) * D + c * 8;
            cp16(sb + arr * 10240 + row * 80 + c * 16, g);
        }
        #pragma unroll
        for (int i = 0; i < 8; i++) {
            const int idx = tid + 256 * i;
            const int row = idx >> 4;
            const int c   = idx & 15;
            const __half* g = d_hn + ((size_t)(b * HW + k0 + row)) * DV + c * 8;
            cp16(sb + 20480 + row * 272 + c * 16, g);
        }
        asm volatile("cp.async.commit_group;");
    };

    const uint32_t koff = ((lane & 7) * KROW + (lane >> 3) * 4) * 4;
    const uint32_t voff = ((lane & 15) * VROW) * 4 + (lane >> 4) * 16;

    issue_tile(0);

    #pragma unroll 1
    for (int t = 0; t < NTILES; t++) {
        if (t + 1 < NTILES) {
            issue_tile(t + 1);
            asm volatile("cp.async.wait_group 1;");
        } else {
            asm volatile("cp.async.wait_group 0;");
        }
        __syncthreads();

        const uint32_t sb = smem_u32 + (t & 1) * BUFB;
        const uint32_t khb = sb + koff;
        const uint32_t vb  = sb + 20480 + voff;

        float s[16][4];
        #pragma unroll
        for (int nt = 0; nt < 16; nt++) {
            uint32_t kh[4], kl[4];
            ldsm4(kh, khb + nt * 640);
            ldsm4(kl, khb + 10240 + nt * 640);
            s[nt][0] = s[nt][1] = s[nt][2] = s[nt][3] = 0.f;
            mma16816(s[nt], qh[0], kh[0], kh[1]);
            mma16816(s[nt], ql[0], kh[0], kh[1]);
            mma16816(s[nt], qh[0], kl[0], kl[1]);
            mma16816(s[nt], qh[1], kh[2], kh[3]);
            mma16816(s[nt], ql[1], kh[2], kh[3]);
            mma16816(s[nt], qh[1], kl[2], kl[3]);
        }

        float mx0 = fmaxf(s[0][0], s[0][1]);
        float mx1 = fmaxf(s[0][2], s[0][3]);
        #pragma unroll
        for (int nt = 1; nt < 16; nt++) {
            mx0 = fmaxf(mx0, fmaxf(s[nt][0], s[nt][1]));
            mx1 = fmaxf(mx1, fmaxf(s[nt][2], s[nt][3]));
        }
        mx0 = fmaxf(mx0, __shfl_xor_sync(0xffffffffu, mx0, 1));
        mx0 = fmaxf(mx0, __shfl_xor_sync(0xffffffffu, mx0, 2));
        mx1 = fmaxf(mx1, __shfl_xor_sync(0xffffffffu, mx1, 1));
        mx1 = fmaxf(mx1, __shfl_xor_sync(0xffffffffu, mx1, 2));

        const float mn0 = fmaxf(mrow0, mx0);
        const float mn1 = fmaxf(mrow1, mx1);
        const float corr0 = exp2f(mrow0 - mn0);
        const float corr1 = exp2f(mrow1 - mn1);
        mrow0 = mn0; mrow1 = mn1;

        // p = exp2(s - mn) computed directly in packed fp16 (1 HMUFU / pair)
        uint32_t pa[8][4];
        #pragma unroll
        for (int nt = 0; nt < 16; nt++) {
            const uint32_t d01 = packh2(s[nt][0] - mn0, s[nt][1] - mn0);
            const uint32_t d23 = packh2(s[nt][2] - mn1, s[nt][3] - mn1);
            uint32_t p01, p23;
            asm("ex2.approx.f16x2 %0, %1;" : "=r"(p01) : "r"(d01));
            asm("ex2.approx.f16x2 %0, %1;" : "=r"(p23) : "r"(d23));
            pa[nt >> 1][(nt & 1) ? 2 : 0] = p01;
            pa[nt >> 1][(nt & 1) ? 3 : 1] = p23;
        }

        lsum[0] *= corr0; lsum[2] *= corr1;
        #pragma unroll
        for (int nt = 0; nt < 16; nt++) {
            o[nt][0] *= corr0; o[nt][1] *= corr0;
            o[nt][2] *= corr1; o[nt][3] *= corr1;
        }

        const uint32_t ONES = 0x3C003C00u;
        #pragma unroll
        for (int ks = 0; ks < 8; ks++) {
            mma16816(lsum, pa[ks], ONES, ONES);
            const uint32_t vrow = vb + ks * 4352;
            #pragma unroll
            for (int ntp = 0; ntp < 8; ntp++) {
                uint32_t v[4];
                ldsm4t(v, vrow + ntp * 32);
                mma16816(o[2 * ntp],     pa[ks], v[0], v[1]);
                mma16816(o[2 * ntp + 1], pa[ks], v[2], v[3]);
            }
        }
        __syncthreads();
    }

    const float inv0 = 1.f / lsum[0];
    const float inv1 = 1.f / lsum[2];
    uint32_t* goh = (uint32_t*)d_obh + ((size_t)b * HW + q0 + w * 16) * 64;
    uint32_t* gol = (uint32_t*)d_obl + ((size_t)b * HW + q0 + w * 16) * 64;
    #pragma unroll
    for (int nt = 0; nt < 16; nt++) {
        uint32_t hi, lo;
        split2(o[nt][0] * inv0, o[nt][1] * inv0, hi, lo);
        goh[lr * 64 + nt * 4 + lc] = hi;
        gol[lr * 64 + nt * 4 + lc] = lo;
        split2(o[nt][2] * inv1, o[nt][3] * inv1, hi, lo);
        goh[(lr + 8) * 64 + nt * 4 + lc] = hi;
        gol[(lr + 8) * 64 + nt * 4 + lc] = lo;
    }
}

// ---------------------------------------------------------------------------
// proj: [65536,256] @ [256,192], fp16 3-term split, cp.async double-buffered.
// Block 128m x 64n, grid (512, 3); 8 warps 4m x 2n, warp tile 32x32.
// Buffer (30720 B): Ah@0, Al@10240, Bh@20480, Bl@25600.
// ---------------------------------------------------------------------------
#define PBUF 30720
__global__ __launch_bounds__(256, 2) void proj_kernel(
    const float* __restrict__ bf, const float* __restrict__ bg,
    const float* __restrict__ bh)
{
    extern __shared__ char smp[];
    const uint32_t sb0 = (uint32_t)__cvta_generic_to_shared(smp);

    const int m0 = blockIdx.x * 128;
    const int by = blockIdx.y;
    const int n0 = by * 64;
    const int tid = threadIdx.x;
    const int lane = tid & 31;
    const int w = tid >> 5;
    const int warpM = (w >> 1) * 32;
    const int warpN = (w & 1) * 32;
    const int lr = lane >> 2, lc = lane & 3;

    auto issue = [&](int s) {
        const uint32_t sb = sb0 + (s & 1) * PBUF;
        const int k0 = s * 32;
        #pragma unroll
        for (int i = 0; i < 4; i++) {          // A hi/lo
            const int idx = tid + 256 * i;
            const int arr = idx >> 9;
            const int row = (idx >> 2) & 127;
            const int c   = idx & 3;
            const __half* g = (arr ? d_xl : d_xh) + (size_t)(m0 + row) * C + k0 + c * 8;
            cp16(sb + arr * 10240 + row * 80 + c * 16, g);
        }
        #pragma unroll
        for (int i = 0; i < 2; i++) {          // B hi/lo
            const int idx = tid + 256 * i;
            const int arr = idx >> 8;
            const int row = (idx >> 2) & 63;
            const int c   = idx & 3;
            const __half* g = (arr ? d_wpl : d_wph) + (size_t)(n0 + row) * C + k0 + c * 8;
            cp16(sb + 20480 + arr * 5120 + row * 80 + c * 16, g);
        }
        asm volatile("cp.async.commit_group;");
    };

    float cfr[2][4][4];
    #pragma unroll
    for (int mt = 0; mt < 2; mt++)
        #pragma unroll
        for (int nt = 0; nt < 4; nt++)
            cfr[mt][nt][0] = cfr[mt][nt][1] = cfr[mt][nt][2] = cfr[mt][nt][3] = 0.f;

    issue(0); issue(1);

    #pragma unroll 1
    for (int s = 0; s < 8; s++) {
        if (s < 7) asm volatile("cp.async.wait_group 1;");
        else       asm volatile("cp.async.wait_group 0;");
        __syncthreads();

        const uint32_t sb = sb0 + (s & 1) * PBUF;

        uint32_t bhf[4][4], blf[4][4];
        #pragma unroll
        for (int g = 0; g < 4; g++) {
            const uint32_t base = sb + 20480 +
                ((warpN + g * 8 + (lane & 7)) * KROW + (lane >> 3) * 4) * 4;
            ldsm4(bhf[g], base);
            ldsm4(blf[g], base + 5120);
        }
        #pragma unroll
        for (int kf = 0; kf < 2; kf++) {
            uint32_t ah[2][4], al[2][4];
            #pragma unroll
            for (int mt = 0; mt < 2; mt++) {
                const uint32_t off = sb +
                    ((warpM + mt * 16 + (lane & 15)) * KROW + kf * 8 + (lane >> 4) * 4) * 4;
                ldsm4(ah[mt], off);
                ldsm4(al[mt], off + 10240);
            }
            #pragma unroll
            for (int mt = 0; mt < 2; mt++)
                #pragma unroll
                for (int nt = 0; nt < 4; nt++) {
                    const uint32_t b0 = bhf[nt][kf * 2], b1 = bhf[nt][kf * 2 + 1];
                    const uint32_t c0 = blf[nt][kf * 2], c1 = blf[nt][kf * 2 + 1];
                    mma16816(cfr[mt][nt], ah[mt], b0, b1);
                    mma16816(cfr[mt][nt], al[mt], b0, b1);
                    mma16816(cfr[mt][nt], ah[mt], c0, c1);
                }
        }
        __syncthreads();
        if (s + 2 < 8) issue(s + 2);
    }

    // epilogue with routing
    #pragma unroll
    for (int mt = 0; mt < 2; mt++) {
        const size_t mA = (size_t)(m0 + warpM + mt * 16 + lr);
        const size_t mB = mA + 8;
        #pragma unroll
        for (int nt = 0; nt < 4; nt++) {
            const int jl = warpN + nt * 8 + 2 * lc;
            const float c0 = cfr[mt][nt][0], c1 = cfr[mt][nt][1];
            const float c2 = cfr[mt][nt][2], c3 = cfr[mt][nt][3];
            if (by == 0) {
                if (jl < 32) {
                    const float b0v = bf[jl], b1v = bf[jl + 1];
                    uint32_t hi, lo;
                    split2(c0 + b0v, c1 + b1v, hi, lo);
                    ((uint32_t*)d_fh)[mA * 16 + (jl >> 1)] = hi;
                    ((uint32_t*)d_fl)[mA * 16 + (jl >> 1)] = lo;
                    split2(c2 + b0v, c3 + b1v, hi, lo);
                    ((uint32_t*)d_fh)[mB * 16 + (jl >> 1)] = hi;
                    ((uint32_t*)d_fl)[mB * 16 + (jl >> 1)] = lo;
                } else {
                    const int jj = jl - 32;
                    const float b0v = bg[jj], b1v = bg[jj + 1];
                    *(float2*)&d_g[mA * D + jj] = make_float2(c0 + b0v, c1 + b1v);
                    *(float2*)&d_g[mB * D + jj] = make_float2(c2 + b0v, c3 + b1v);
                }
            } else {
                const int dv = (by - 1) * 64 + jl;
                const float b0v = bh[dv], b1v = bh[dv + 1];
                ((uint32_t*)d_hn)[mA * 64 + (dv >> 1)] = packh2(c0 + b0v, c1 + b1v);
                ((uint32_t*)d_hn)[mB * 64 + (dv >> 1)] = packh2(c2 + b0v, c3 + b1v);
            }
        }
    }
}

// ---------------------------------------------------------------------------
// outproj: out = x + O @ Wo + bo, fp16 3-term, fully double-buffered.
// Block 128m x 128n, grid (512, 2); 8 warps 2m x 4n, warp tile 64x32.
// Buffer (40960 B): Ah@0, Al@10240, Bh@20480, Bl@30720.
// ---------------------------------------------------------------------------
#define OBUF 40960
__global__ __launch_bounds__(256, 1) void outproj_kernel(
    const float* __restrict__ x,
    const float* __restrict__ bo,
    float* __restrict__ out)
{
    extern __shared__ char smo[];
    const uint32_t sb0 = (uint32_t)__cvta_generic_to_shared(smo);

    const int m0 = blockIdx.x * 128;
    const int n0 = blockIdx.y * 128;
    const int tid = threadIdx.x;
    const int lane = tid & 31;
    const int w = tid >> 5;
    const int warpM = (w >> 2) * 64;
    const int warpN = (w & 3) * 32;
    const int lr = lane >> 2, lc = lane & 3;

    auto issue = [&](int s) {
        const uint32_t sb = sb0 + (s & 1) * OBUF;
        const int k0 = s * 32;
        #pragma unroll
        for (int i = 0; i < 4; i++) {          // A hi/lo
            const int idx = tid + 256 * i;
            const int arr = idx >> 9;
            const int row = (idx >> 2) & 127;
            const int c   = idx & 3;
            const __half* g = (arr ? d_obl : d_obh) + (size_t)(m0 + row) * DV + k0 + c * 8;
            cp16(sb + arr * 10240 + row * 80 + c * 16, g);
        }
        #pragma unroll
        for (int i = 0; i < 4; i++) {          // B hi/lo
            const int idx = tid + 256 * i;
            const int arr = idx >> 9;
            const int row = (idx >> 2) & 127;
            const int c   = idx & 3;
            const __half* g = (arr ? d_wol : d_woh) + (size_t)(n0 + row) * DV + k0 + c * 8;
            cp16(sb + 20480 + arr * 10240 + row * 80 + c * 16, g);
        }
        asm volatile("cp.async.commit_group;");
    };

    float cfr[4][4][4];
    #pragma unroll
    for (int mt = 0; mt < 4; mt++)
        #pragma unroll
        for (int nt = 0; nt < 4; nt++)
            cfr[mt][nt][0] = cfr[mt][nt][1] = cfr[mt][nt][2] = cfr[mt][nt][3] = 0.f;

    issue(0); issue(1);

    #pragma unroll 1
    for (int s = 0; s < 4; s++) {
        if (s < 3) asm volatile("cp.async.wait_group 1;");
        else       asm volatile("cp.async.wait_group 0;");
        __syncthreads();

        const uint32_t sb = sb0 + (s & 1) * OBUF;

        uint32_t bhf[4][4], blf[4][4];
        #pragma unroll
        for (int g = 0; g < 4; g++) {
            const uint32_t base = sb + 20480 +
                ((warpN + g * 8 + (lane & 7)) * KROW + (lane >> 3) * 4) * 4;
            ldsm4(bhf[g], base);
            ldsm4(blf[g], base + 10240);
        }
        #pragma unroll
        for (int kf = 0; kf < 2; kf++) {
            uint32_t ah[4][4], al[4][4];
            #pragma unroll
            for (int mt = 0; mt < 4; mt++) {
                const uint32_t off = sb +
                    ((warpM + mt * 16 + (lane & 15)) * KROW + kf * 8 + (lane >> 4) * 4) * 4;
                ldsm4(ah[mt], off);
                ldsm4(al[mt], off + 10240);
            }
            #pragma unroll
            for (int mt = 0; mt < 4; mt++)
                #pragma unroll
                for (int nt = 0; nt < 4; nt++) {
                    const uint32_t b0 = bhf[nt][kf * 2], b1 = bhf[nt][kf * 2 + 1];
                    const uint32_t c0 = blf[nt][kf * 2], c1 = blf[nt][kf * 2 + 1];
                    mma16816(cfr[mt][nt], ah[mt], b0, b1);
                    mma16816(cfr[mt][nt], al[mt], b0, b1);
                    mma16816(cfr[mt][nt], ah[mt], c0, c1);
                }
        }
        __syncthreads();
        if (s + 2 < 4) issue(s + 2);
    }

    // epilogue: bias + residual
    #pragma unroll
    for (int mt = 0; mt < 4; mt++) {
        const size_t mA = (size_t)(m0 + warpM + mt * 16 + lr);
        const size_t mB = mA + 8;
        #pragma unroll
        for (int nt = 0; nt < 4; nt++) {
            const int j = n0 + warpN + nt * 8 + 2 * lc;
            const float b0v = bo[j], b1v = bo[j + 1];
            const float2 xa = *(const float2*)&x[mA * C + j];
            const float2 xb = *(const float2*)&x[mB * C + j];
            *(float2*)&out[mA * C + j] =
                make_float2(xa.x + cfr[mt][nt][0] + b0v, xa.y + cfr[mt][nt][1] + b1v);
            *(float2*)&out[mB * C + j] =
                make_float2(xb.x + cfr[mt][nt][2] + b0v, xb.y + cfr[mt][nt][3] + b1v);
        }
    }
}

// ---------------------------------------------------------------------------
extern "C" void kernel_launch(void* const* d_in, const int* in_sizes, int n_in,
                              void* d_out, int out_size)
{
    const float* x  = (const float*)d_in[0];
    const float* Wf = (const float*)d_in[1];
    const float* bf = (const float*)d_in[2];
    const float* Wg = (const float*)d_in[3];
    const float* bg = (const float*)d_in[4];
    const float* Wh = (const float*)d_in[5];
    const float* bh = (const float*)d_in[6];
    const float* Wo = (const float*)d_in[7];
    const float* bo = (const float*)d_in[8];
    float* out = (float*)d_out;

    presplit_x_kernel<<<2048, 256>>>(x);
    presplit_w_kernel<<<320, 256>>>(Wf, Wg, Wh, Wo);

    const int smem_proj = 2 * PBUF;   // 61440
    cudaFuncSetAttribute(proj_kernel,
                         cudaFuncAttributeMaxDynamicSharedMemorySize, smem_proj);
    proj_kernel<<<dim3(M_TOTAL / 128, 3), 256, smem_proj>>>(bf, bg, bh);

    const int smem_attn = 2 * BUFB;   // 110592
    cudaFuncSetAttribute(attn_kernel,
                         cudaFuncAttributeMaxDynamicSharedMemorySize, smem_attn);
    attn_kernel<<<dim3(HW / TQ, BATCH), 256, smem_attn>>>();

    const int smem_op = 2 * OBUF;     // 81920
    cudaFuncSetAttribute(outproj_kernel,
                         cudaFuncAttributeMaxDynamicSharedMemorySize, smem_op);
    outproj_kernel<<<dim3(M_TOTAL / 128, C / 128), 256, smem_op>>>(x, bo, out);
}